// round 15
// baseline (speedup 1.0000x reference)
#include <cuda_runtime.h>

// AnalyticalBoundedLineAttractor — analytic piecewise-affine ODE integrator.
//
// Per step: z = Wx + b; m = (z>0); x' = x + p1 + p2 with
//   p1 = DT*(relu(z) - x),  p2 = (m .* (W'p1) - DT*p1)/2,  W' = DT*W.
// K = 2 Taylor terms (measured rel_err 4.6e-4 vs 1e-3 gate; K=1 would be
// ~5e-2, so 2 matvecs/step is the truncation minimum).
// Identity: W'p1 = W'relu(z) - DT*(W'x); dot 2 runs on relu(z), the
// -DT*W'x piece folds into off-path algebra (dwx = z - db).
//
// Architecture = measured optimum across 14 rounds: 2 elements per
// 128-thread CTA, grid=128 (one CTA/SM, 4 warps on 4 SMSPs), per-element
// NAMED 64-thread bar.sync exchange (beats CTA-wide bar +75%, shuffles
// +57%, warp-private syncwarp +23%, arrive/sync splits +3-4%, dual-chain
// ILP +64%), dot = 16 LDS.128 + 32 fma.rn.f32x2 with 4 packed
// accumulators (2 accs = zero RAW slack, regresses), DT*b seeded into
// dot-1's accumulator, relu exchanged (not p1), sel+fma tails, 99 stored
// updates (x_100 never needed), time loop unroll 1.
//
// R15 micro-trims vs R11 (the only on-chain ops left):
//  - next-step c1xi/dxi FMULs moved from loop top (post-bar, on chain)
//    into the post-STS pre-bar shadow.
//  - trajectory STG issued before the xs STS so the smem store the bar
//    drains is last.

#define DIMV 64
#define DTC  0.05f

using u64 = unsigned long long;

__device__ __forceinline__ u64 fma2(u64 a, u64 b, u64 c) {
    u64 d; asm("fma.rn.f32x2 %0, %1, %2, %3;" : "=l"(d) : "l"(a), "l"(b), "l"(c));
    return d;
}
__device__ __forceinline__ u64 add2(u64 a, u64 b) {
    u64 d; asm("add.rn.f32x2 %0, %1, %2;" : "=l"(d) : "l"(a), "l"(b));
    return d;
}
__device__ __forceinline__ u64 pack2(float lo, float hi) {
    u64 d; asm("mov.b64 %0, {%1, %2};" : "=l"(d) : "f"(lo), "f"(hi));
    return d;
}

__global__ void __launch_bounds__(128, 1)
attractor_kernel(const float* __restrict__ x0,
                 const float* __restrict__ Wg,
                 const float* __restrict__ bg,
                 float* __restrict__ out,
                 int tsteps)
{
    __shared__ __align__(16) float xs[2][DIMV];    // x exchange buffer
    __shared__ __align__(16) float rs[2][DIMV];    // relu(z) exchange buffer

    const int tid  = threadIdx.x;
    const int el   = tid >> 6;                     // local element 0/1
    const int i    = tid & 63;                     // row index
    const int elem = blockIdx.x * 2 + el;
    const int bar  = el + 1;                       // named barrier id

    // ---- W row i, pre-scaled by DT, as 32 packed f32x2 pairs ----
    u64 w2[32];
    {
        const float* wrow = Wg + i * DIMV;
#pragma unroll
        for (int q = 0; q < 16; q++) {
            float4 t = reinterpret_cast<const float4*>(wrow)[q];
            w2[2*q]   = pack2(t.x * DTC, t.y * DTC);
            w2[2*q+1] = pack2(t.z * DTC, t.w * DTC);
        }
    }
    const float db  = DTC * bg[i];                 // DT * b_i
    const u64 dbin  = pack2(db, 0.f);              // dot-1 accumulator seed
    float xi = x0[(size_t)elem * DIMV + i];

    xs[el][i] = xi;
    float* outp = out + (size_t)elem * tsteps * DIMV + i;
    *outp = xi;                                    // x_0 stored up front
    float c1xi = (1.0f - DTC) * xi;                // next-step precomputes
    float dxi  = DTC * xi;
    asm volatile("bar.sync %0, 64;" :: "r"(bar) : "memory");

    // dot(DT*W_row_i, buf) + seed: 16 x LDS.128 + 32 x fma.f32x2, 4 accs
    auto dot = [&](const float* buf, u64 seed) -> float {
        const ulonglong2* p16 = reinterpret_cast<const ulonglong2*>(buf);
        u64 a0 = seed, a1 = 0ull, a2 = 0ull, a3 = 0ull;
#pragma unroll
        for (int q = 0; q < 16; q += 2) {
            ulonglong2 v0 = p16[q];
            ulonglong2 v1 = p16[q + 1];
            a0 = fma2(w2[2*q + 0], v0.x, a0);
            a1 = fma2(w2[2*q + 1], v0.y, a1);
            a2 = fma2(w2[2*q + 2], v1.x, a2);
            a3 = fma2(w2[2*q + 3], v1.y, a3);
        }
        u64 s = add2(add2(a0, a1), add2(a2, a3));
        float lo, hi;
        asm("mov.b64 {%0, %1}, %2;" : "=f"(lo), "=f"(hi) : "l"(s));
        return lo + hi;
    };

    // 99 updates: x_100 is never stored, so never computed.
#pragma unroll 1
    for (int t = 1; t < tsteps; t++) {
        // dot 1: z = (W'x)_i + DT*b_i straight out of the tree
        float z    = dot(xs[el], dbin);
        float relu = fmaxf(z, 0.f);                // FMNMX, lat 4
        rs[el][i]  = relu;                         // exchange relu(z)
        asm volatile("bar.sync %0, 64;" :: "r"(bar) : "memory");

        // off critical path (overlaps barrier + dot-2 LDS/FMA stream):
        //   p1 = relu - DT*x ; dwx = z - db
        //   inner2 = x + p1 - (DT/2) p1 - m * (DT/2) dwx
        bool  m      = z > 0.f;
        float p1     = relu - dxi;
        float dwx    = z - db;
        float inner  = fmaf(-0.5f * DTC, p1, relu + c1xi);
        float inner2 = inner - (m ? 0.5f * DTC * dwx : 0.f);

        // dot 2: t2 = (W' relu)_i ; x' = inner2 + 0.5 * (m ? t2 : 0)
        float t2 = dot(rs[el], 0ull);
        xi = fmaf(m ? t2 : 0.f, 0.5f, inner2);     // sel + fma only

        outp += DIMV;
        *outp = xi;                                // off-chain trajectory store
        xs[el][i] = xi;                            // readers retired at bar above
        c1xi = (1.0f - DTC) * xi;                  // next-step precomputes in
        dxi  = DTC * xi;                           //   the bar shadow
        asm volatile("bar.sync %0, 64;" :: "r"(bar) : "memory");
    }
}

extern "C" void kernel_launch(void* const* d_in, const int* in_sizes, int n_in,
                              void* d_out, int out_size)
{
    const float* x0 = (const float*)d_in[0];   // (batch, 64)
    const float* W  = (const float*)d_in[1];   // (64, 64)
    const float* b  = (const float*)d_in[2];   // (64,)
    float* out = (float*)d_out;                // (batch, T, 64)

    int batch  = in_sizes[0] / DIMV;           // 256
    int tsteps = out_size / (batch * DIMV);    // 100

    attractor_kernel<<<batch / 2, 128>>>(x0, W, b, out, tsteps);
}

// round 16
// speedup vs baseline: 1.0036x; 1.0036x over previous
#include <cuda_runtime.h>

// AnalyticalBoundedLineAttractor — analytic piecewise-affine ODE integrator.
//
// Per step: z = Wx + b; m = (z>0); x' = x + p1 + p2 with
//   p1 = DT*(relu(z) - x),  p2 = (m .* (W'p1) - DT*p1)/2,  W' = DT*W.
// K = 2 Taylor terms (measured rel_err 4.6e-4 vs 1e-3 gate; K=1 would be
// ~5e-2, so 2 matvecs/step is the truncation minimum).
// Identity: W'p1 = W'relu(z) - DT*(W'x); dot 2 runs on relu(z), the
// -DT*W'x piece folds into off-path algebra (dwx = z - db).
//
// Architecture = measured optimum across 15 rounds: 2 elements per
// 128-thread CTA, grid=128 (one CTA/SM, 4 warps on 4 SMSPs), per-element
// NAMED 64-thread bar.sync exchange (beats CTA-wide bar +75%, shuffles
// +57%, warp-private syncwarp +23%, arrive/sync splits +3-4%, dual-chain
// ILP +64%), dot = 16 LDS.128 + 32 fma.rn.f32x2 with 4 packed
// accumulators (2 accs = zero RAW slack, regresses), DT*b seeded into
// dot-1's accumulator, relu exchanged (not p1), sel+fma tails, 99 stored
// updates (x_100 never needed), time loop unroll 1, off-path algebra in
// the barrier/LDS shadows.
//
// R16: last-iteration peel — the final iteration's xs STS, loop-end bar,
// and next-step precomputes are dead (no consumer); the tail block ends
// at the trajectory store. Loop body byte-identical to R15.

#define DIMV 64
#define DTC  0.05f

using u64 = unsigned long long;

__device__ __forceinline__ u64 fma2(u64 a, u64 b, u64 c) {
    u64 d; asm("fma.rn.f32x2 %0, %1, %2, %3;" : "=l"(d) : "l"(a), "l"(b), "l"(c));
    return d;
}
__device__ __forceinline__ u64 add2(u64 a, u64 b) {
    u64 d; asm("add.rn.f32x2 %0, %1, %2;" : "=l"(d) : "l"(a), "l"(b));
    return d;
}
__device__ __forceinline__ u64 pack2(float lo, float hi) {
    u64 d; asm("mov.b64 %0, {%1, %2};" : "=l"(d) : "f"(lo), "f"(hi));
    return d;
}

__global__ void __launch_bounds__(128, 1)
attractor_kernel(const float* __restrict__ x0,
                 const float* __restrict__ Wg,
                 const float* __restrict__ bg,
                 float* __restrict__ out,
                 int tsteps)
{
    __shared__ __align__(16) float xs[2][DIMV];    // x exchange buffer
    __shared__ __align__(16) float rs[2][DIMV];    // relu(z) exchange buffer

    const int tid  = threadIdx.x;
    const int el   = tid >> 6;                     // local element 0/1
    const int i    = tid & 63;                     // row index
    const int elem = blockIdx.x * 2 + el;
    const int bar  = el + 1;                       // named barrier id

    // ---- W row i, pre-scaled by DT, as 32 packed f32x2 pairs ----
    u64 w2[32];
    {
        const float* wrow = Wg + i * DIMV;
#pragma unroll
        for (int q = 0; q < 16; q++) {
            float4 t = reinterpret_cast<const float4*>(wrow)[q];
            w2[2*q]   = pack2(t.x * DTC, t.y * DTC);
            w2[2*q+1] = pack2(t.z * DTC, t.w * DTC);
        }
    }
    const float db  = DTC * bg[i];                 // DT * b_i
    const u64 dbin  = pack2(db, 0.f);              // dot-1 accumulator seed
    float xi = x0[(size_t)elem * DIMV + i];

    xs[el][i] = xi;
    float* outp = out + (size_t)elem * tsteps * DIMV + i;
    *outp = xi;                                    // x_0 stored up front
    float c1xi = (1.0f - DTC) * xi;                // next-step precomputes
    float dxi  = DTC * xi;
    asm volatile("bar.sync %0, 64;" :: "r"(bar) : "memory");

    // dot(DT*W_row_i, buf) + seed: 16 x LDS.128 + 32 x fma.f32x2, 4 accs
    auto dot = [&](const float* buf, u64 seed) -> float {
        const ulonglong2* p16 = reinterpret_cast<const ulonglong2*>(buf);
        u64 a0 = seed, a1 = 0ull, a2 = 0ull, a3 = 0ull;
#pragma unroll
        for (int q = 0; q < 16; q += 2) {
            ulonglong2 v0 = p16[q];
            ulonglong2 v1 = p16[q + 1];
            a0 = fma2(w2[2*q + 0], v0.x, a0);
            a1 = fma2(w2[2*q + 1], v0.y, a1);
            a2 = fma2(w2[2*q + 2], v1.x, a2);
            a3 = fma2(w2[2*q + 3], v1.y, a3);
        }
        u64 s = add2(add2(a0, a1), add2(a2, a3));
        float lo, hi;
        asm("mov.b64 {%0, %1}, %2;" : "=f"(lo), "=f"(hi) : "l"(s));
        return lo + hi;
    };

    // one full step: dot1 -> relu exchange -> dot2 -> x'
    auto step_core = [&]() -> float {
        // dot 1: z = (W'x)_i + DT*b_i straight out of the tree
        float z    = dot(xs[el], dbin);
        float relu = fmaxf(z, 0.f);                // FMNMX, lat 4
        rs[el][i]  = relu;                         // exchange relu(z)
        asm volatile("bar.sync %0, 64;" :: "r"(bar) : "memory");

        // off critical path (overlaps barrier + dot-2 LDS/FMA stream):
        bool  m      = z > 0.f;
        float p1     = relu - dxi;
        float dwx    = z - db;
        float inner  = fmaf(-0.5f * DTC, p1, relu + c1xi);
        float inner2 = inner - (m ? 0.5f * DTC * dwx : 0.f);

        // dot 2: t2 = (W' relu)_i ; x' = inner2 + 0.5 * (m ? t2 : 0)
        float t2 = dot(rs[el], 0ull);
        return fmaf(m ? t2 : 0.f, 0.5f, inner2);   // sel + fma only
    };

    // iterations 1 .. tsteps-2 (full body incl. republish + loop-end bar)
#pragma unroll 1
    for (int t = 1; t < tsteps - 1; t++) {
        xi = step_core();
        outp += DIMV;
        *outp = xi;                                // off-chain trajectory store
        xs[el][i] = xi;                            // readers retired at bar above
        c1xi = (1.0f - DTC) * xi;                  // next-step precomputes in
        dxi  = DTC * xi;                           //   the bar shadow
        asm volatile("bar.sync %0, 64;" :: "r"(bar) : "memory");
    }

    // final iteration (t = tsteps-1): no consumer follows — skip the xs
    // STS, the loop-end bar, and the dead precomputes.
    xi = step_core();
    outp += DIMV;
    *outp = xi;
}

extern "C" void kernel_launch(void* const* d_in, const int* in_sizes, int n_in,
                              void* d_out, int out_size)
{
    const float* x0 = (const float*)d_in[0];   // (batch, 64)
    const float* W  = (const float*)d_in[1];   // (64, 64)
    const float* b  = (const float*)d_in[2];   // (64,)
    float* out = (float*)d_out;                // (batch, T, 64)

    int batch  = in_sizes[0] / DIMV;           // 256
    int tsteps = out_size / (batch * DIMV);    // 100

    attractor_kernel<<<batch / 2, 128>>>(x0, W, b, out, tsteps);
}